// round 16
// baseline (speedup 1.0000x reference)
#include <cuda_runtime.h>
#include <cuda_fp16.h>
#include <math.h>
#include <stdint.h>

#define B_  4
#define S_  2048
#define D_  1024
#define H_  16
#define DK_ 64
#define M_  (B_*S_)   // 8192

typedef unsigned long long u64;
typedef unsigned int u32;

// ===================== warp-level tensor-core helpers (non-"a" ISA) ========
__device__ __forceinline__ u32 smem_to_u32(const void* p) {
    u32 a;
    asm("{ .reg .u64 t; cvta.to.shared.u64 t, %1; cvt.u32.u64 %0, t; }"
        : "=r"(a) : "l"(p));
    return a;
}
__device__ __forceinline__ void ldsm4(u32& r0, u32& r1, u32& r2, u32& r3, u32 a) {
    asm volatile("ldmatrix.sync.aligned.m8n8.x4.shared.b16 {%0,%1,%2,%3}, [%4];"
                 : "=r"(r0), "=r"(r1), "=r"(r2), "=r"(r3) : "r"(a));
}
__device__ __forceinline__ void ldsm4t(u32& r0, u32& r1, u32& r2, u32& r3, u32 a) {
    asm volatile("ldmatrix.sync.aligned.m8n8.x4.trans.shared.b16 {%0,%1,%2,%3}, [%4];"
                 : "=r"(r0), "=r"(r1), "=r"(r2), "=r"(r3) : "r"(a));
}
// fp16 operands, fp32 accumulate (main term)
__device__ __forceinline__ void mma_f32acc(float* c, const u32* a, u32 b0, u32 b1) {
    asm volatile("mma.sync.aligned.m16n8k16.row.col.f32.f16.f16.f32 "
                 "{%0,%1,%2,%3}, {%4,%5,%6,%7}, {%8,%9}, {%0,%1,%2,%3};"
                 : "+f"(c[0]), "+f"(c[1]), "+f"(c[2]), "+f"(c[3])
                 : "r"(a[0]), "r"(a[1]), "r"(a[2]), "r"(a[3]), "r"(b0), "r"(b1));
}
// fp16 operands, fp16 accumulate (correction terms — possible 2x rate)
__device__ __forceinline__ void mma_f16acc(u32* c, const u32* a, u32 b0, u32 b1) {
    asm volatile("mma.sync.aligned.m16n8k16.row.col.f16.f16.f16.f16 "
                 "{%0,%1}, {%2,%3,%4,%5}, {%6,%7}, {%0,%1};"
                 : "+r"(c[0]), "+r"(c[1])
                 : "r"(a[0]), "r"(a[1]), "r"(a[2]), "r"(a[3]), "r"(b0), "r"(b1));
}
// pack (hi, lo) floats -> f16x2 register (lower half = lo)
__device__ __forceinline__ u32 pkhf(float hi, float lo) {
    __half2 h = __floats2half2_rn(lo, hi);
    return *reinterpret_cast<u32*>(&h);
}
__device__ __forceinline__ float2 h2f2(u32 v) {
    __half2 h = *reinterpret_cast<__half2*>(&v);
    return __half22float2(h);
}
__device__ __forceinline__ float hf_lo(u32 v) { return h2f2(v).x; }
__device__ __forceinline__ float hf_hi(u32 v) { return h2f2(v).y; }

#define CP_ASYNC16(saddr, gptr) \
    asm volatile("cp.async.cg.shared.global [%0], [%1], 16;" \
                 :: "r"(saddr), "l"(gptr))
#define CP_COMMIT()  asm volatile("cp.async.commit_group;" ::: "memory")
#define CP_WAIT0()   asm volatile("cp.async.wait_group 0;" ::: "memory")

// ---------------- scratch (device globals: allocation-free) ----------------
__device__ __half g_ih[3][M_*D_];   // input splits (q,k,v) hi; [0] reused for attn out
__device__ __half g_il[3][M_*D_];   // input splits lo
__device__ __half g_wh[4][D_*D_];   // weight splits hi (Wq,Wk,Wv,Wo)
__device__ __half g_wl[4][D_*D_];   // weight splits lo
__device__ __half g_qh[M_*D_];
__device__ __half g_ql[M_*D_];
__device__ __half g_kh[M_*D_];
__device__ __half g_kl[M_*D_];
__device__ __half g_vh[M_*D_];
__device__ __half g_vl[M_*D_];

// ---------------------------------------------------------------------------
// one-launch split of all 7 fp32 tensors -> f16 hi + lo
// ---------------------------------------------------------------------------
struct CArgs {
    const float* src[7];
    __half* h[7];
    __half* l[7];
    int n4[7];
};

__global__ __launch_bounds__(256)
void cvt_split7(CArgs ca)
{
    const int z = blockIdx.y;
    const int i = blockIdx.x * 256 + threadIdx.x;
    if (i >= ca.n4[z]) return;
    float4 v = ((const float4*)ca.src[z])[i];
    __half h0 = __float2half_rn(v.x), h1 = __float2half_rn(v.y);
    __half h2 = __float2half_rn(v.z), h3 = __float2half_rn(v.w);
    __half l0 = __float2half_rn(v.x - __half2float(h0));
    __half l1 = __float2half_rn(v.y - __half2float(h1));
    __half l2 = __float2half_rn(v.z - __half2float(h2));
    __half l3 = __float2half_rn(v.w - __half2float(h3));
    ((__half2*)ca.h[z])[2*i+0] = __halves2half2(h0, h1);
    ((__half2*)ca.h[z])[2*i+1] = __halves2half2(h2, h3);
    ((__half2*)ca.l[z])[2*i+0] = __halves2half2(l0, l1);
    ((__half2*)ca.l[z])[2*i+1] = __halves2half2(l2, l3);
}

// ---------------------------------------------------------------------------
// cp.async double-buffered mma.sync fp16x3 GEMM (operands pre-split f16):
//   C[z] = (Ah+Al)[z][M,K] @ (Wh+Wl)[z][N,K]^T + bias[z]
// Main term Ah*Wh in f32-acc; corrections Al*Wh + Ah*Wl in f16-acc.
// CTA 128x128, K-chunk 64, 16 warps (warp tile 64x16).
// ---------------------------------------------------------------------------
#define GEMM_SMEM (2*4*16384)   // 131072

struct GArgs2 {
    const __half* Ah[3];
    const __half* Al[3];
    const __half* Wh[3];
    const __half* Wl[3];
    const float* bias[3];
    __half* Ch[3];
    __half* Cl[3];
    float* Cf[3];
};

template<int OUT_SPLIT>
__global__ __launch_bounds__(512)
void gemm_mma(GArgs2 ga)
{
    extern __shared__ char smc[];
    const u32 sb   = smem_to_u32(smc);
    const int tid  = threadIdx.x, wid = tid >> 5, lane = tid & 31;
    const int z    = blockIdx.z;
    const int brow = blockIdx.y * 128, bcol = blockIdx.x * 128;
    const int wm   = wid & 1;        // 0/1 -> 64-row half
    const int wn   = wid >> 1;       // 0..7 -> 16-col slice
    const int lr   = lane & 15, lhi = lane >> 4;

    const __half* Ahg = ga.Ah[z];
    const __half* Alg = ga.Al[z];
    const __half* Whg = ga.Wh[z];
    const __half* Wlg = ga.Wl[z];

    float accf[4][2][4];
    u32   acch[4][2][2];
    #pragma unroll
    for (int mt = 0; mt < 4; mt++)
        #pragma unroll
        for (int nt = 0; nt < 2; nt++) {
            #pragma unroll
            for (int r = 0; r < 4; r++) accf[mt][nt][r] = 0.f;
            acch[mt][nt][0] = 0u; acch[mt][nt][1] = 0u;
        }

    auto load_chunk = [&](int c, int bufb) {
        const int k0 = c * 64;
        const u32 base = sb + (u32)bufb * 65536u;
        #pragma unroll
        for (int seg = tid; seg < 1024; seg += 512) {
            int r = seg >> 3, s2 = seg & 7;
            u32 off = (u32)(r*128 + s2*16); off ^= (off >> 3) & 0x70;
            size_t ga_off = (size_t)(brow + r) * D_ + k0 + s2*8;
            size_t gw_off = (size_t)(bcol + r) * D_ + k0 + s2*8;
            CP_ASYNC16(base + off,          Ahg + ga_off);
            CP_ASYNC16(base + off + 16384,  Alg + ga_off);
            CP_ASYNC16(base + off + 32768,  Whg + gw_off);
            CP_ASYNC16(base + off + 49152,  Wlg + gw_off);
        }
        CP_COMMIT();
    };

    load_chunk(0, 0);

    for (int c = 0; c < 16; c++) {
        CP_WAIT0();
        __syncthreads();
        if (c < 15) load_chunk(c + 1, (c + 1) & 1);

        const u32 sa = sb + (u32)(c & 1) * 65536u;

        #pragma unroll
        for (int ks = 0; ks < 4; ks++) {
            u32 ah[4][4], al[4][4];
            #pragma unroll
            for (int mt = 0; mt < 4; mt++) {
                int r = wm*64 + mt*16 + lr;
                u32 off = (u32)(r*128 + (ks*2 + lhi)*16);
                off ^= (off >> 3) & 0x70;
                ldsm4(ah[mt][0], ah[mt][1], ah[mt][2], ah[mt][3], sa + off);
                ldsm4(al[mt][0], al[mt][1], al[mt][2], al[mt][3], sa + 16384 + off);
            }
            u32 bh[4], bl[4];
            {
                int r = wn*16 + lr;
                u32 off = (u32)(r*128 + (ks*2 + lhi)*16);
                off ^= (off >> 3) & 0x70;
                ldsm4(bh[0], bh[1], bh[2], bh[3], sa + 32768 + off);
                ldsm4(bl[0], bl[1], bl[2], bl[3], sa + 49152 + off);
            }
            // main: Ah*Wh (f32 acc)
            #pragma unroll
            for (int half = 0; half < 2; half++)
                #pragma unroll
                for (int mt = 0; mt < 4; mt++)
                    mma_f32acc(accf[mt][half], ah[mt], bh[half], bh[half+2]);
            // corr: Al*Wh (f16 acc)
            #pragma unroll
            for (int half = 0; half < 2; half++)
                #pragma unroll
                for (int mt = 0; mt < 4; mt++)
                    mma_f16acc(acch[mt][half], al[mt], bh[half], bh[half+2]);
            // corr: Ah*Wl (f16 acc)
            #pragma unroll
            for (int half = 0; half < 2; half++)
                #pragma unroll
                for (int mt = 0; mt < 4; mt++)
                    mma_f16acc(acch[mt][half], ah[mt], bl[half], bl[half+2]);
        }
    }

    const float* bias = ga.bias[z];
    const int r0 = lane >> 2, c0 = (lane & 3) * 2;
    #pragma unroll
    for (int nt = 0; nt < 2; nt++) {
        const int col = bcol + wn*16 + nt*8 + c0;
        float2 bv = *(const float2*)&bias[col];
        #pragma unroll
        for (int mt = 0; mt < 4; mt++) {
            const int row = brow + wm*64 + mt*16 + r0;
            float2 p0 = h2f2(acch[mt][nt][0]);   // (c0,c1) row r
            float2 p1 = h2f2(acch[mt][nt][1]);   // (c2,c3) row r+8
            float a0 = accf[mt][nt][0] + p0.x + bv.x;
            float a1 = accf[mt][nt][1] + p0.y + bv.y;
            float a2 = accf[mt][nt][2] + p1.x + bv.x;
            float a3 = accf[mt][nt][3] + p1.y + bv.y;
            if (OUT_SPLIT) {
                __half* Ch = ga.Ch[z];
                __half* Cl = ga.Cl[z];
                u32 h01 = pkhf(a1, a0);
                u32 h23 = pkhf(a3, a2);
                u32 l01 = pkhf(a1 - hf_hi(h01), a0 - hf_lo(h01));
                u32 l23 = pkhf(a3 - hf_hi(h23), a2 - hf_lo(h23));
                *(u32*)(Ch + (size_t)row     * D_ + col) = h01;
                *(u32*)(Ch + (size_t)(row+8) * D_ + col) = h23;
                *(u32*)(Cl + (size_t)row     * D_ + col) = l01;
                *(u32*)(Cl + (size_t)(row+8) * D_ + col) = l23;
            } else {
                float* Cf = ga.Cf[z];
                *(float2*)(Cf + (size_t)row     * D_ + col) = make_float2(a0, a1);
                *(float2*)(Cf + (size_t)(row+8) * D_ + col) = make_float2(a2, a3);
            }
        }
    }
}

// ---------------------------------------------------------------------------
// Causal flash attention, tensor cores, fp16x3 splits (main f32-acc,
// corrections f16-acc), fp32 softmax. Block = (b,h) x 128 q-rows, 8 warps.
// K/V 64-row tiles, cp.async double-buffered. Fully-masked 16-wide
// QK col-blocks and 16-tall PV row-blocks are skipped (warp-uniform).
// ---------------------------------------------------------------------------
#define FA_SMEM (32768 + 2*32768)   // 96 KB

__device__ __forceinline__ void fa_load_kv(char* dst,
    const __half* __restrict__ kh, const __half* __restrict__ kl,
    const __half* __restrict__ vh, const __half* __restrict__ vl,
    size_t gbase, int tid)
{
    #pragma unroll
    for (int seg = tid; seg < 512; seg += 256) {
        int r = seg >> 3, c = seg & 7;
        u32 off = (u32)(r*128 + c*16); off ^= (off >> 3) & 0x70;
        size_t g = gbase + (size_t)r * D_ + c*8;
        u32 s0 = smem_to_u32(dst + off);
        CP_ASYNC16(s0,         kh + g);
        CP_ASYNC16(s0 + 8192,  kl + g);
        CP_ASYNC16(s0 + 16384, vh + g);
        CP_ASYNC16(s0 + 24576, vl + g);
    }
    CP_COMMIT();
}

__global__ __launch_bounds__(256)
void flash_attn_mma(const __half* __restrict__ qh, const __half* __restrict__ ql,
                    const __half* __restrict__ kh, const __half* __restrict__ kl,
                    const __half* __restrict__ vh, const __half* __restrict__ vl,
                    __half* __restrict__ oh, __half* __restrict__ ol)
{
    extern __shared__ char smf[];
    const u32 sb = smem_to_u32(smf);
    const int tid = threadIdx.x, w = tid >> 5, lane = tid & 31;
    const int qb = (int)gridDim.x - 1 - (int)blockIdx.x;   // big tiles first
    const int q0 = qb * 128;
    const int b = blockIdx.y >> 4, h = blockIdx.y & 15;
    const size_t rowbase = (size_t)b * S_;
    const size_t colbase = (size_t)h * 64;

    const int lr = lane & 15, lhi = lane >> 4;
    const int r0 = lane >> 2, cq = (lane & 3) * 2;
    const int rg = w*16 + r0;
    const int wtop = w*16 + 15;   // warp's max q-row within the tile

    {
        const __half* gh = qh + (rowbase + q0) * D_ + colbase;
        const __half* gl = ql + (rowbase + q0) * D_ + colbase;
        #pragma unroll
        for (int seg = tid; seg < 1024; seg += 256) {
            int r = seg >> 3, c = seg & 7;
            u32 off = (u32)(r*128 + c*16); off ^= (off >> 3) & 0x70;
            *(uint4*)(smf + off)         = *(const uint4*)(gh + (size_t)r * D_ + c*8);
            *(uint4*)(smf + 16384 + off) = *(const uint4*)(gl + (size_t)r * D_ + c*8);
        }
    }

    const int ttmax = 2*qb + 1;
    fa_load_kv(smf + 32768, kh, kl, vh, vl, rowbase * D_ + colbase, tid);

    float m0 = -INFINITY, m1 = -INFINITY, l0 = 0.f, l1 = 0.f;
    float o[8][4];
    #pragma unroll
    for (int nt = 0; nt < 8; nt++)
        #pragma unroll
        for (int r = 0; r < 4; r++) o[nt][r] = 0.f;

    for (int tt = 0; tt <= ttmax; tt++) {
        CP_WAIT0();
        __syncthreads();
        if (tt < ttmax)
            fa_load_kv(smf + 32768 + ((tt+1)&1)*32768, kh, kl, vh, vl,
                       (rowbase + (size_t)(tt+1)*64) * D_ + colbase, tid);

        const int dcol = tt*64 - q0;
        if (dcol > wtop) continue;

        const u32 sk = sb + 32768u + (u32)(tt & 1) * 32768u;

        float s[8][4];
        u32 sh[8][2];
        #pragma unroll
        for (int nt = 0; nt < 8; nt++) {
            #pragma unroll
            for (int r = 0; r < 4; r++) s[nt][r] = 0.f;
            sh[nt][0] = 0u; sh[nt][1] = 0u;
        }

        #pragma unroll
        for (int ks = 0; ks < 4; ks++) {
            u32 offA = (u32)((w*16 + lr)*128 + (ks*2 + lhi)*16);
            offA ^= (offA >> 3) & 0x70;
            u32 aqh[4], aql[4];
            ldsm4(aqh[0], aqh[1], aqh[2], aqh[3], sb + offA);
            ldsm4(aql[0], aql[1], aql[2], aql[3], sb + 16384 + offA);
            #pragma unroll
            for (int np = 0; np < 4; np++) {
                if (dcol + np*16 > wtop) continue;   // fully-masked col block
                u32 kb[4], kr[4];
                u32 offB = (u32)((np*16 + lr)*128 + (ks*2 + lhi)*16);
                offB ^= (offB >> 3) & 0x70;
                ldsm4(kb[0], kb[1], kb[2], kb[3], sk + offB);
                ldsm4(kr[0], kr[1], kr[2], kr[3], sk + 8192 + offB);
                mma_f32acc(s[np*2+0], aqh, kb[0], kb[2]);
                mma_f32acc(s[np*2+1], aqh, kb[1], kb[3]);
                mma_f16acc(sh[np*2+0], aql, kb[0], kb[2]);
                mma_f16acc(sh[np*2+1], aql, kb[1], kb[3]);
                mma_f16acc(sh[np*2+0], aqh, kr[0], kr[2]);
                mma_f16acc(sh[np*2+1], aqh, kr[1], kr[3]);
            }
        }
        // merge f16-acc corrections into fp32 scores
        #pragma unroll
        for (int nt = 0; nt < 8; nt++) {
            float2 p0 = h2f2(sh[nt][0]);
            float2 p1 = h2f2(sh[nt][1]);
            s[nt][0] += p0.x; s[nt][1] += p0.y;
            s[nt][2] += p1.x; s[nt][3] += p1.y;
        }

        if (dcol + 63 > w*16) {
            #pragma unroll
            for (int nt = 0; nt < 8; nt++) {
                const int cc = nt*8 + cq + dcol;
                if (cc     > rg)     s[nt][0] = -INFINITY;
                if (cc + 1 > rg)     s[nt][1] = -INFINITY;
                if (cc     > rg + 8) s[nt][2] = -INFINITY;
                if (cc + 1 > rg + 8) s[nt][3] = -INFINITY;
            }
        }

        float rm0 = -INFINITY, rm1 = -INFINITY;
        #pragma unroll
        for (int nt = 0; nt < 8; nt++) {
            rm0 = fmaxf(rm0, fmaxf(s[nt][0], s[nt][1]));
            rm1 = fmaxf(rm1, fmaxf(s[nt][2], s[nt][3]));
        }
        rm0 = fmaxf(rm0, __shfl_xor_sync(0xffffffffu, rm0, 1));
        rm0 = fmaxf(rm0, __shfl_xor_sync(0xffffffffu, rm0, 2));
        rm1 = fmaxf(rm1, __shfl_xor_sync(0xffffffffu, rm1, 1));
        rm1 = fmaxf(rm1, __shfl_xor_sync(0xffffffffu, rm1, 2));
        float mn0 = fmaxf(m0, rm0), mn1 = fmaxf(m1, rm1);
        float alpha0 = __expf(0.125f * (m0 - mn0));
        float alpha1 = __expf(0.125f * (m1 - mn1));
        m0 = mn0; m1 = mn1;
        const float m08 = mn0 * 0.125f, m18 = mn1 * 0.125f;
        float rs0 = 0.f, rs1 = 0.f;
        #pragma unroll
        for (int nt = 0; nt < 8; nt++) {
            s[nt][0] = __expf(fmaf(s[nt][0], 0.125f, -m08));
            s[nt][1] = __expf(fmaf(s[nt][1], 0.125f, -m08));
            s[nt][2] = __expf(fmaf(s[nt][2], 0.125f, -m18));
            s[nt][3] = __expf(fmaf(s[nt][3], 0.125f, -m18));
            rs0 += s[nt][0] + s[nt][1];
            rs1 += s[nt][2] + s[nt][3];
        }
        rs0 += __shfl_xor_sync(0xffffffffu, rs0, 1);
        rs0 += __shfl_xor_sync(0xffffffffu, rs0, 2);
        rs1 += __shfl_xor_sync(0xffffffffu, rs1, 1);
        rs1 += __shfl_xor_sync(0xffffffffu, rs1, 2);
        l0 = l0 * alpha0 + rs0;
        l1 = l1 * alpha1 + rs1;
        #pragma unroll
        for (int nt = 0; nt < 8; nt++) {
            o[nt][0] *= alpha0; o[nt][1] *= alpha0;
            o[nt][2] *= alpha1; o[nt][3] *= alpha1;
        }

        // ---- O += P V : main f32-acc, corrections f16-acc ----
        u32 ohc[8][2];
        #pragma unroll
        for (int nt = 0; nt < 8; nt++) { ohc[nt][0] = 0u; ohc[nt][1] = 0u; }

        #pragma unroll
        for (int kt = 0; kt < 4; kt++) {
            if (dcol + kt*16 > wtop) continue;   // P block entirely zero
            u32 aph[4], apl[4];
            #pragma unroll
            for (int half = 0; half < 2; half++) {
                const float plo0 = s[2*kt + half][0], phi0 = s[2*kt + half][1];
                const float plo1 = s[2*kt + half][2], phi1 = s[2*kt + half][3];
                u32 h0 = pkhf(phi0, plo0);
                u32 h1 = pkhf(phi1, plo1);
                aph[0 + 2*half] = h0;
                aph[1 + 2*half] = h1;
                apl[0 + 2*half] = pkhf(phi0 - hf_hi(h0), plo0 - hf_lo(h0));
                apl[1 + 2*half] = pkhf(phi1 - hf_hi(h1), plo1 - hf_lo(h1));
            }
            #pragma unroll
            for (int ng2 = 0; ng2 < 4; ng2++) {
                u32 offV = (u32)((kt*16 + lr)*128 + ng2*32 + lhi*16);
                offV ^= (offV >> 3) & 0x70;
                u32 v4h[4], v4l[4];
                ldsm4t(v4h[0], v4h[1], v4h[2], v4h[3], sk + 16384 + offV);
                ldsm4t(v4l[0], v4l[1], v4l[2], v4l[3], sk + 24576 + offV);
                mma_f32acc(o[ng2*2],   aph, v4h[0], v4h[1]);
                mma_f32acc(o[ng2*2+1], aph, v4h[2], v4h[3]);
                mma_f16acc(ohc[ng2*2],   apl, v4h[0], v4h[1]);
                mma_f16acc(ohc[ng2*2+1], apl, v4h[2], v4h[3]);
                mma_f16acc(ohc[ng2*2],   aph, v4l[0], v4l[1]);
                mma_f16acc(ohc[ng2*2+1], aph, v4l[2], v4l[3]);
            }
        }
        // merge PV corrections into fp32 output accumulators
        #pragma unroll
        for (int nt = 0; nt < 8; nt++) {
            float2 p0 = h2f2(ohc[nt][0]);
            float2 p1 = h2f2(ohc[nt][1]);
            o[nt][0] += p0.x; o[nt][1] += p0.y;
            o[nt][2] += p1.x; o[nt][3] += p1.y;
        }
    }

    const float inv0 = 1.f / l0, inv1 = 1.f / l1;
    const size_t orow = (rowbase + q0 + rg) * D_ + colbase;
    #pragma unroll
    for (int nt = 0; nt < 8; nt++) {
        const int col = nt*8 + cq;
        float a0 = o[nt][0]*inv0, a1 = o[nt][1]*inv0;
        float a2 = o[nt][2]*inv1, a3 = o[nt][3]*inv1;
        u32 h01 = pkhf(a1, a0);
        u32 h23 = pkhf(a3, a2);
        u32 l01 = pkhf(a1 - hf_hi(h01), a0 - hf_lo(h01));
        u32 l23 = pkhf(a3 - hf_hi(h23), a2 - hf_lo(h23));
        *(u32*)(oh + orow + col)        = h01;
        *(u32*)(oh + orow + 8*D_ + col) = h23;
        *(u32*)(ol + orow + col)        = l01;
        *(u32*)(ol + orow + 8*D_ + col) = l23;
    }
}

// ---------------------------------------------------------------------------
extern "C" void kernel_launch(void* const* d_in, const int* in_sizes, int n_in,
                              void* d_out, int out_size)
{
    const float* q  = (const float*)d_in[0];
    const float* k  = (const float*)d_in[1];
    const float* v  = (const float*)d_in[2];
    const float* Wq = (const float*)d_in[3];
    const float* bq = (const float*)d_in[4];
    const float* Wk = (const float*)d_in[5];
    const float* bk = (const float*)d_in[6];
    const float* Wv = (const float*)d_in[7];
    const float* bv = (const float*)d_in[8];
    const float* Wo = (const float*)d_in[9];
    const float* bo = (const float*)d_in[10];
    float* out = (float*)d_out;

    __half *ih, *il, *wh, *wl, *qhp, *qlp, *khp, *klp, *vhp, *vlp;
    cudaGetSymbolAddress((void**)&ih, g_ih);
    cudaGetSymbolAddress((void**)&il, g_il);
    cudaGetSymbolAddress((void**)&wh, g_wh);
    cudaGetSymbolAddress((void**)&wl, g_wl);
    cudaGetSymbolAddress((void**)&qhp, g_qh);
    cudaGetSymbolAddress((void**)&qlp, g_ql);
    cudaGetSymbolAddress((void**)&khp, g_kh);
    cudaGetSymbolAddress((void**)&klp, g_kl);
    cudaGetSymbolAddress((void**)&vhp, g_vh);
    cudaGetSymbolAddress((void**)&vlp, g_vl);

    const size_t NX = (size_t)M_ * D_;
    const size_t NW = (size_t)D_ * D_;

    cudaFuncSetAttribute(gemm_mma<1>,
                         cudaFuncAttributeMaxDynamicSharedMemorySize, GEMM_SMEM);
    cudaFuncSetAttribute(gemm_mma<0>,
                         cudaFuncAttributeMaxDynamicSharedMemorySize, GEMM_SMEM);
    cudaFuncSetAttribute(flash_attn_mma,
                         cudaFuncAttributeMaxDynamicSharedMemorySize, FA_SMEM);

    // one launch: split q,k,v + all 4 weights into f16 hi/lo
    CArgs ca = {};
    ca.src[0] = q;  ca.h[0] = ih;        ca.l[0] = il;        ca.n4[0] = (int)(NX/4);
    ca.src[1] = k;  ca.h[1] = ih + NX;   ca.l[1] = il + NX;   ca.n4[1] = (int)(NX/4);
    ca.src[2] = v;  ca.h[2] = ih + 2*NX; ca.l[2] = il + 2*NX; ca.n4[2] = (int)(NX/4);
    ca.src[3] = Wq; ca.h[3] = wh;        ca.l[3] = wl;        ca.n4[3] = (int)(NW/4);
    ca.src[4] = Wk; ca.h[4] = wh + NW;   ca.l[4] = wl + NW;   ca.n4[4] = (int)(NW/4);
    ca.src[5] = Wv; ca.h[5] = wh + 2*NW; ca.l[5] = wl + 2*NW; ca.n4[5] = (int)(NW/4);
    ca.src[6] = Wo; ca.h[6] = wh + 3*NW; ca.l[6] = wl + 3*NW; ca.n4[6] = (int)(NW/4);
    cvt_split7<<<dim3((unsigned)(NX/4/256), 7), 256>>>(ca);

    // fused Q/K/V projections, cp.async double-buffered, 512 threads
    GArgs2 gq = {};
    gq.Ah[0] = ih;        gq.Al[0] = il;        gq.Wh[0] = wh;        gq.Wl[0] = wl;
    gq.Ah[1] = ih + NX;   gq.Al[1] = il + NX;   gq.Wh[1] = wh + NW;   gq.Wl[1] = wl + NW;
    gq.Ah[2] = ih + 2*NX; gq.Al[2] = il + 2*NX; gq.Wh[2] = wh + 2*NW; gq.Wl[2] = wl + 2*NW;
    gq.bias[0] = bq; gq.bias[1] = bk; gq.bias[2] = bv;
    gq.Ch[0] = qhp; gq.Ch[1] = khp; gq.Ch[2] = vhp;
    gq.Cl[0] = qlp; gq.Cl[1] = klp; gq.Cl[2] = vlp;
    gemm_mma<1><<<dim3(D_/128, M_/128, 3), 512, GEMM_SMEM>>>(gq);

    // attention: writes f16 hi/lo splits into the (now free) q-input buffers
    flash_attn_mma<<<dim3(S_/128, B_*H_), 256, FA_SMEM>>>(qhp, qlp, khp, klp,
                                                           vhp, vlp, ih, il);

    // output projection (fp32 out)
    GArgs2 go = {};
    go.Ah[0] = ih; go.Al[0] = il;
    go.Wh[0] = wh + 3*NW; go.Wl[0] = wl + 3*NW;
    go.bias[0] = bo;
    go.Cf[0] = out;
    gemm_mma<0><<<dim3(D_/128, M_/128, 1), 512, GEMM_SMEM>>>(go);
}

// round 17
// speedup vs baseline: 1.3796x; 1.3796x over previous
#include <cuda_runtime.h>
#include <cuda_fp16.h>
#include <math.h>
#include <stdint.h>

#define B_  4
#define S_  2048
#define D_  1024
#define H_  16
#define DK_ 64
#define M_  (B_*S_)   // 8192

typedef unsigned long long u64;
typedef unsigned int u32;

// ===================== warp-level tensor-core helpers (non-"a" ISA) ========
__device__ __forceinline__ u32 smem_to_u32(const void* p) {
    u32 a;
    asm("{ .reg .u64 t; cvta.to.shared.u64 t, %1; cvt.u32.u64 %0, t; }"
        : "=r"(a) : "l"(p));
    return a;
}
__device__ __forceinline__ void ldsm4(u32& r0, u32& r1, u32& r2, u32& r3, u32 a) {
    asm volatile("ldmatrix.sync.aligned.m8n8.x4.shared.b16 {%0,%1,%2,%3}, [%4];"
                 : "=r"(r0), "=r"(r1), "=r"(r2), "=r"(r3) : "r"(a));
}
__device__ __forceinline__ void ldsm4t(u32& r0, u32& r1, u32& r2, u32& r3, u32 a) {
    asm volatile("ldmatrix.sync.aligned.m8n8.x4.trans.shared.b16 {%0,%1,%2,%3}, [%4];"
                 : "=r"(r0), "=r"(r1), "=r"(r2), "=r"(r3) : "r"(a));
}
// fp16 operands, fp32 accumulate (main term)
__device__ __forceinline__ void mma_f32acc(float* c, const u32* a, u32 b0, u32 b1) {
    asm volatile("mma.sync.aligned.m16n8k16.row.col.f32.f16.f16.f32 "
                 "{%0,%1,%2,%3}, {%4,%5,%6,%7}, {%8,%9}, {%0,%1,%2,%3};"
                 : "+f"(c[0]), "+f"(c[1]), "+f"(c[2]), "+f"(c[3])
                 : "r"(a[0]), "r"(a[1]), "r"(a[2]), "r"(a[3]), "r"(b0), "r"(b1));
}
// fp16 operands, fp16 accumulate (correction term)
__device__ __forceinline__ void mma_f16acc(u32* c, const u32* a, u32 b0, u32 b1) {
    asm volatile("mma.sync.aligned.m16n8k16.row.col.f16.f16.f16.f16 "
                 "{%0,%1}, {%2,%3,%4,%5}, {%6,%7}, {%0,%1};"
                 : "+r"(c[0]), "+r"(c[1])
                 : "r"(a[0]), "r"(a[1]), "r"(a[2]), "r"(a[3]), "r"(b0), "r"(b1));
}
// pack (hi, lo) floats -> f16x2 register (lower half = lo)
__device__ __forceinline__ u32 pkhf(float hi, float lo) {
    __half2 h = __floats2half2_rn(lo, hi);
    return *reinterpret_cast<u32*>(&h);
}
__device__ __forceinline__ float2 h2f2(u32 v) {
    __half2 h = *reinterpret_cast<__half2*>(&v);
    return __half22float2(h);
}
__device__ __forceinline__ float hf_lo(u32 v) { return h2f2(v).x; }
__device__ __forceinline__ float hf_hi(u32 v) { return h2f2(v).y; }

#define CP_ASYNC16(saddr, gptr) \
    asm volatile("cp.async.cg.shared.global [%0], [%1], 16;" \
                 :: "r"(saddr), "l"(gptr))
#define CP_COMMIT()  asm volatile("cp.async.commit_group;" ::: "memory")
#define CP_WAIT0()   asm volatile("cp.async.wait_group 0;" ::: "memory")

// ---------------- scratch (device globals: allocation-free) ----------------
__device__ __half g_ih[3][M_*D_];   // input hi (q,k,v); [0]+[1] reused for attn out hi/lo
__device__ __half g_il[3][M_*D_];   // input lo
__device__ __half g_wh[4][D_*D_];   // weight hi (Wq,Wk,Wv,Wo) — lo never needed (B-side)
__device__ __half g_qh[M_*D_];
__device__ __half g_ql[M_*D_];
__device__ __half g_kh[M_*D_];      // K hi only (B-side of QK^T)
__device__ __half g_vh[M_*D_];      // V hi only (B-side of PV)

// ---------------------------------------------------------------------------
// one-launch split of all 7 fp32 tensors -> f16 hi (+ lo when needed)
// ---------------------------------------------------------------------------
struct CArgs {
    const float* src[7];
    __half* h[7];
    __half* l[7];     // nullptr -> hi only
    int n4[7];
};

__global__ __launch_bounds__(256)
void cvt_split7(CArgs ca)
{
    const int z = blockIdx.y;
    const int i = blockIdx.x * 256 + threadIdx.x;
    if (i >= ca.n4[z]) return;
    float4 v = ((const float4*)ca.src[z])[i];
    __half h0 = __float2half_rn(v.x), h1 = __float2half_rn(v.y);
    __half h2 = __float2half_rn(v.z), h3 = __float2half_rn(v.w);
    ((__half2*)ca.h[z])[2*i+0] = __halves2half2(h0, h1);
    ((__half2*)ca.h[z])[2*i+1] = __halves2half2(h2, h3);
    if (ca.l[z]) {
        __half l0 = __float2half_rn(v.x - __half2float(h0));
        __half l1 = __float2half_rn(v.y - __half2float(h1));
        __half l2 = __float2half_rn(v.z - __half2float(h2));
        __half l3 = __float2half_rn(v.w - __half2float(h3));
        ((__half2*)ca.l[z])[2*i+0] = __halves2half2(l0, l1);
        ((__half2*)ca.l[z])[2*i+1] = __halves2half2(l2, l3);
    }
}

// ---------------------------------------------------------------------------
// cp.async double-buffered mma.sync fp16x2 GEMM:
//   C[z] = (Ah+Al)[z][M,K] @ Wh[z][N,K]^T + bias[z]
// Main term Ah*Wh in f32-acc; correction Al*Wh in f16-acc. (a*Wl dropped:
// ~2^-12 relative — inside the 1e-3 budget.)
// CTA 128x128, K-chunk 64, 16 warps (warp tile 64x16). smem 2x48KB.
// ---------------------------------------------------------------------------
#define GEMM_SMEM (2*3*16384)   // 98304

struct GArgs2 {
    const __half* Ah[3];
    const __half* Al[3];
    const __half* Wh[3];
    const float* bias[3];
    __half* Ch[3];
    __half* Cl[3];    // nullptr -> hi only
    float* Cf[3];
};

template<int OUT_SPLIT>
__global__ __launch_bounds__(512)
void gemm_mma(GArgs2 ga)
{
    extern __shared__ char smc[];
    const u32 sb   = smem_to_u32(smc);
    const int tid  = threadIdx.x, wid = tid >> 5, lane = tid & 31;
    const int z    = blockIdx.z;
    const int brow = blockIdx.y * 128, bcol = blockIdx.x * 128;
    const int wm   = wid & 1;        // 0/1 -> 64-row half
    const int wn   = wid >> 1;       // 0..7 -> 16-col slice
    const int lr   = lane & 15, lhi = lane >> 4;

    const __half* Ahg = ga.Ah[z];
    const __half* Alg = ga.Al[z];
    const __half* Whg = ga.Wh[z];

    float accf[4][2][4];
    u32   acch[4][2][2];
    #pragma unroll
    for (int mt = 0; mt < 4; mt++)
        #pragma unroll
        for (int nt = 0; nt < 2; nt++) {
            #pragma unroll
            for (int r = 0; r < 4; r++) accf[mt][nt][r] = 0.f;
            acch[mt][nt][0] = 0u; acch[mt][nt][1] = 0u;
        }

    auto load_chunk = [&](int c, int bufb) {
        const int k0 = c * 64;
        const u32 base = sb + (u32)bufb * 49152u;
        #pragma unroll
        for (int seg = tid; seg < 1024; seg += 512) {
            int r = seg >> 3, s2 = seg & 7;
            u32 off = (u32)(r*128 + s2*16); off ^= (off >> 3) & 0x70;
            size_t ga_off = (size_t)(brow + r) * D_ + k0 + s2*8;
            size_t gw_off = (size_t)(bcol + r) * D_ + k0 + s2*8;
            CP_ASYNC16(base + off,          Ahg + ga_off);
            CP_ASYNC16(base + off + 16384,  Alg + ga_off);
            CP_ASYNC16(base + off + 32768,  Whg + gw_off);
        }
        CP_COMMIT();
    };

    load_chunk(0, 0);

    for (int c = 0; c < 16; c++) {
        CP_WAIT0();
        __syncthreads();
        if (c < 15) load_chunk(c + 1, (c + 1) & 1);

        const u32 sa = sb + (u32)(c & 1) * 49152u;

        #pragma unroll
        for (int ks = 0; ks < 4; ks++) {
            u32 ah[4][4], al[4][4];
            #pragma unroll
            for (int mt = 0; mt < 4; mt++) {
                int r = wm*64 + mt*16 + lr;
                u32 off = (u32)(r*128 + (ks*2 + lhi)*16);
                off ^= (off >> 3) & 0x70;
                ldsm4(ah[mt][0], ah[mt][1], ah[mt][2], ah[mt][3], sa + off);
                ldsm4(al[mt][0], al[mt][1], al[mt][2], al[mt][3], sa + 16384 + off);
            }
            u32 bh[4];
            {
                int r = wn*16 + lr;
                u32 off = (u32)(r*128 + (ks*2 + lhi)*16);
                off ^= (off >> 3) & 0x70;
                ldsm4(bh[0], bh[1], bh[2], bh[3], sa + 32768 + off);
            }
            // main: Ah*Wh (f32 acc)
            #pragma unroll
            for (int half = 0; half < 2; half++)
                #pragma unroll
                for (int mt = 0; mt < 4; mt++)
                    mma_f32acc(accf[mt][half], ah[mt], bh[half], bh[half+2]);
            // corr: Al*Wh (f16 acc)
            #pragma unroll
            for (int half = 0; half < 2; half++)
                #pragma unroll
                for (int mt = 0; mt < 4; mt++)
                    mma_f16acc(acch[mt][half], al[mt], bh[half], bh[half+2]);
        }
    }

    const float* bias = ga.bias[z];
    const int r0 = lane >> 2, c0 = (lane & 3) * 2;
    #pragma unroll
    for (int nt = 0; nt < 2; nt++) {
        const int col = bcol + wn*16 + nt*8 + c0;
        float2 bv = *(const float2*)&bias[col];
        #pragma unroll
        for (int mt = 0; mt < 4; mt++) {
            const int row = brow + wm*64 + mt*16 + r0;
            float2 p0 = h2f2(acch[mt][nt][0]);
            float2 p1 = h2f2(acch[mt][nt][1]);
            float a0 = accf[mt][nt][0] + p0.x + bv.x;
            float a1 = accf[mt][nt][1] + p0.y + bv.y;
            float a2 = accf[mt][nt][2] + p1.x + bv.x;
            float a3 = accf[mt][nt][3] + p1.y + bv.y;
            if (OUT_SPLIT) {
                __half* Ch = ga.Ch[z];
                __half* Cl = ga.Cl[z];
                u32 h01 = pkhf(a1, a0);
                u32 h23 = pkhf(a3, a2);
                *(u32*)(Ch + (size_t)row     * D_ + col) = h01;
                *(u32*)(Ch + (size_t)(row+8) * D_ + col) = h23;
                if (Cl) {
                    u32 l01 = pkhf(a1 - hf_hi(h01), a0 - hf_lo(h01));
                    u32 l23 = pkhf(a3 - hf_hi(h23), a2 - hf_lo(h23));
                    *(u32*)(Cl + (size_t)row     * D_ + col) = l01;
                    *(u32*)(Cl + (size_t)(row+8) * D_ + col) = l23;
                }
            } else {
                float* Cf = ga.Cf[z];
                *(float2*)(Cf + (size_t)row     * D_ + col) = make_float2(a0, a1);
                *(float2*)(Cf + (size_t)(row+8) * D_ + col) = make_float2(a2, a3);
            }
        }
    }
}

// ---------------------------------------------------------------------------
// Causal flash attention: S = (Qh+Ql)*Kh^T, O = (Ph+Pl)*Vh.
// Main terms f32-acc, corrections f16-acc; fp32 softmax.
// Block = (b,h) x 128 q-rows, 8 warps. K/V 64-row hi-only tiles (16KB),
// cp.async double-buffered. Warp-uniform skip of fully-masked blocks.
// smem: Qh 16K | Ql 16K | 2 x [Kh 8K | Vh 8K] = 64 KB
// ---------------------------------------------------------------------------
#define FA_SMEM (32768 + 2*16384)   // 65536

__device__ __forceinline__ void fa_load_kv(char* dst,
    const __half* __restrict__ kh, const __half* __restrict__ vh,
    size_t gbase, int tid)
{
    #pragma unroll
    for (int seg = tid; seg < 512; seg += 256) {
        int r = seg >> 3, c = seg & 7;
        u32 off = (u32)(r*128 + c*16); off ^= (off >> 3) & 0x70;
        size_t g = gbase + (size_t)r * D_ + c*8;
        u32 s0 = smem_to_u32(dst + off);
        CP_ASYNC16(s0,        kh + g);
        CP_ASYNC16(s0 + 8192, vh + g);
    }
    CP_COMMIT();
}

__global__ __launch_bounds__(256)
void flash_attn_mma(const __half* __restrict__ qh, const __half* __restrict__ ql,
                    const __half* __restrict__ kh, const __half* __restrict__ vh,
                    __half* __restrict__ oh, __half* __restrict__ ol)
{
    extern __shared__ char smf[];
    const u32 sb = smem_to_u32(smf);
    const int tid = threadIdx.x, w = tid >> 5, lane = tid & 31;
    const int qb = (int)gridDim.x - 1 - (int)blockIdx.x;   // big tiles first
    const int q0 = qb * 128;
    const int b = blockIdx.y >> 4, h = blockIdx.y & 15;
    const size_t rowbase = (size_t)b * S_;
    const size_t colbase = (size_t)h * 64;

    const int lr = lane & 15, lhi = lane >> 4;
    const int r0 = lane >> 2, cq = (lane & 3) * 2;
    const int rg = w*16 + r0;
    const int wtop = w*16 + 15;   // warp's max q-row within the tile

    {
        const __half* gh = qh + (rowbase + q0) * D_ + colbase;
        const __half* gl = ql + (rowbase + q0) * D_ + colbase;
        #pragma unroll
        for (int seg = tid; seg < 1024; seg += 256) {
            int r = seg >> 3, c = seg & 7;
            u32 off = (u32)(r*128 + c*16); off ^= (off >> 3) & 0x70;
            *(uint4*)(smf + off)         = *(const uint4*)(gh + (size_t)r * D_ + c*8);
            *(uint4*)(smf + 16384 + off) = *(const uint4*)(gl + (size_t)r * D_ + c*8);
        }
    }

    const int ttmax = 2*qb + 1;
    fa_load_kv(smf + 32768, kh, vh, rowbase * D_ + colbase, tid);

    float m0 = -INFINITY, m1 = -INFINITY, l0 = 0.f, l1 = 0.f;
    float o[8][4];
    #pragma unroll
    for (int nt = 0; nt < 8; nt++)
        #pragma unroll
        for (int r = 0; r < 4; r++) o[nt][r] = 0.f;

    for (int tt = 0; tt <= ttmax; tt++) {
        CP_WAIT0();
        __syncthreads();
        if (tt < ttmax)
            fa_load_kv(smf + 32768 + ((tt+1)&1)*16384, kh, vh,
                       (rowbase + (size_t)(tt+1)*64) * D_ + colbase, tid);

        const int dcol = tt*64 - q0;
        if (dcol > wtop) continue;

        const u32 sk = sb + 32768u + (u32)(tt & 1) * 16384u;

        float s[8][4];
        u32 sh[8][2];
        #pragma unroll
        for (int nt = 0; nt < 8; nt++) {
            #pragma unroll
            for (int r = 0; r < 4; r++) s[nt][r] = 0.f;
            sh[nt][0] = 0u; sh[nt][1] = 0u;
        }

        #pragma unroll
        for (int ks = 0; ks < 4; ks++) {
            u32 offA = (u32)((w*16 + lr)*128 + (ks*2 + lhi)*16);
            offA ^= (offA >> 3) & 0x70;
            u32 aqh[4], aql[4];
            ldsm4(aqh[0], aqh[1], aqh[2], aqh[3], sb + offA);
            ldsm4(aql[0], aql[1], aql[2], aql[3], sb + 16384 + offA);
            #pragma unroll
            for (int np = 0; np < 4; np++) {
                if (dcol + np*16 > wtop) continue;   // fully-masked col block
                u32 kb[4];
                u32 offB = (u32)((np*16 + lr)*128 + (ks*2 + lhi)*16);
                offB ^= (offB >> 3) & 0x70;
                ldsm4(kb[0], kb[1], kb[2], kb[3], sk + offB);
                mma_f32acc(s[np*2+0], aqh, kb[0], kb[2]);
                mma_f32acc(s[np*2+1], aqh, kb[1], kb[3]);
                mma_f16acc(sh[np*2+0], aql, kb[0], kb[2]);
                mma_f16acc(sh[np*2+1], aql, kb[1], kb[3]);
            }
        }
        // merge f16-acc corrections into fp32 scores
        #pragma unroll
        for (int nt = 0; nt < 8; nt++) {
            float2 p0 = h2f2(sh[nt][0]);
            float2 p1 = h2f2(sh[nt][1]);
            s[nt][0] += p0.x; s[nt][1] += p0.y;
            s[nt][2] += p1.x; s[nt][3] += p1.y;
        }

        if (dcol + 63 > w*16) {
            #pragma unroll
            for (int nt = 0; nt < 8; nt++) {
                const int cc = nt*8 + cq + dcol;
                if (cc     > rg)     s[nt][0] = -INFINITY;
                if (cc + 1 > rg)     s[nt][1] = -INFINITY;
                if (cc     > rg + 8) s[nt][2] = -INFINITY;
                if (cc + 1 > rg + 8) s[nt][3] = -INFINITY;
            }
        }

        float rm0 = -INFINITY, rm1 = -INFINITY;
        #pragma unroll
        for (int nt = 0; nt < 8; nt++) {
            rm0 = fmaxf(rm0, fmaxf(s[nt][0], s[nt][1]));
            rm1 = fmaxf(rm1, fmaxf(s[nt][2], s[nt][3]));
        }
        rm0 = fmaxf(rm0, __shfl_xor_sync(0xffffffffu, rm0, 1));
        rm0 = fmaxf(rm0, __shfl_xor_sync(0xffffffffu, rm0, 2));
        rm1 = fmaxf(rm1, __shfl_xor_sync(0xffffffffu, rm1, 1));
        rm1 = fmaxf(rm1, __shfl_xor_sync(0xffffffffu, rm1, 2));
        float mn0 = fmaxf(m0, rm0), mn1 = fmaxf(m1, rm1);
        float alpha0 = __expf(0.125f * (m0 - mn0));
        float alpha1 = __expf(0.125f * (m1 - mn1));
        m0 = mn0; m1 = mn1;
        const float m08 = mn0 * 0.125f, m18 = mn1 * 0.125f;
        float rs0 = 0.f, rs1 = 0.f;
        #pragma unroll
        for (int nt = 0; nt < 8; nt++) {
            s[nt][0] = __expf(fmaf(s[nt][0], 0.125f, -m08));
            s[nt][1] = __expf(fmaf(s[nt][1], 0.125f, -m08));
            s[nt][2] = __expf(fmaf(s[nt][2], 0.125f, -m18));
            s[nt][3] = __expf(fmaf(s[nt][3], 0.125f, -m18));
            rs0 += s[nt][0] + s[nt][1];
            rs1 += s[nt][2] + s[nt][3];
        }
        rs0 += __shfl_xor_sync(0xffffffffu, rs0, 1);
        rs0 += __shfl_xor_sync(0xffffffffu, rs0, 2);
        rs1 += __shfl_xor_sync(0xffffffffu, rs1, 1);
        rs1 += __shfl_xor_sync(0xffffffffu, rs1, 2);
        l0 = l0 * alpha0 + rs0;
        l1 = l1 * alpha1 + rs1;
        #pragma unroll
        for (int nt = 0; nt < 8; nt++) {
            o[nt][0] *= alpha0; o[nt][1] *= alpha0;
            o[nt][2] *= alpha1; o[nt][3] *= alpha1;
        }

        // ---- O += P V : main f32-acc, correction f16-acc ----
        u32 ohc[8][2];
        #pragma unroll
        for (int nt = 0; nt < 8; nt++) { ohc[nt][0] = 0u; ohc[nt][1] = 0u; }

        #pragma unroll
        for (int kt = 0; kt < 4; kt++) {
            if (dcol + kt*16 > wtop) continue;   // P block entirely zero
            u32 aph[4], apl[4];
            #pragma unroll
            for (int half = 0; half < 2; half++) {
                const float plo0 = s[2*kt + half][0], phi0 = s[2*kt + half][1];
                const float plo1 = s[2*kt + half][2], phi1 = s[2*kt + half][3];
                u32 h0 = pkhf(phi0, plo0);
                u32 h1 = pkhf(phi1, plo1);
                aph[0 + 2*half] = h0;
                aph[1 + 2*half] = h1;
                apl[0 + 2*half] = pkhf(phi0 - hf_hi(h0), plo0 - hf_lo(h0));
                apl[1 + 2*half] = pkhf(phi1 - hf_hi(h1), plo1 - hf_lo(h1));
            }
            #pragma unroll
            for (int ng2 = 0; ng2 < 4; ng2++) {
                u32 offV = (u32)((kt*16 + lr)*128 + ng2*32 + lhi*16);
                offV ^= (offV >> 3) & 0x70;
                u32 v4h[4];
                ldsm4t(v4h[0], v4h[1], v4h[2], v4h[3], sk + 8192 + offV);
                mma_f32acc(o[ng2*2],   aph, v4h[0], v4h[1]);
                mma_f32acc(o[ng2*2+1], aph, v4h[2], v4h[3]);
                mma_f16acc(ohc[ng2*2],   apl, v4h[0], v4h[1]);
                mma_f16acc(ohc[ng2*2+1], apl, v4h[2], v4h[3]);
            }
        }
        // merge PV corrections
        #pragma unroll
        for (int nt = 0; nt < 8; nt++) {
            float2 p0 = h2f2(ohc[nt][0]);
            float2 p1 = h2f2(ohc[nt][1]);
            o[nt][0] += p0.x; o[nt][1] += p0.y;
            o[nt][2] += p1.x; o[nt][3] += p1.y;
        }
    }

    const float inv0 = 1.f / l0, inv1 = 1.f / l1;
    const size_t orow = (rowbase + q0 + rg) * D_ + colbase;
    #pragma unroll
    for (int nt = 0; nt < 8; nt++) {
        const int col = nt*8 + cq;
        float a0 = o[nt][0]*inv0, a1 = o[nt][1]*inv0;
        float a2 = o[nt][2]*inv1, a3 = o[nt][3]*inv1;
        u32 h01 = pkhf(a1, a0);
        u32 h23 = pkhf(a3, a2);
        u32 l01 = pkhf(a1 - hf_hi(h01), a0 - hf_lo(h01));
        u32 l23 = pkhf(a3 - hf_hi(h23), a2 - hf_lo(h23));
        *(u32*)(oh + orow + col)        = h01;
        *(u32*)(oh + orow + 8*D_ + col) = h23;
        *(u32*)(ol + orow + col)        = l01;
        *(u32*)(ol + orow + 8*D_ + col) = l23;
    }
}

// ---------------------------------------------------------------------------
extern "C" void kernel_launch(void* const* d_in, const int* in_sizes, int n_in,
                              void* d_out, int out_size)
{
    const float* q  = (const float*)d_in[0];
    const float* k  = (const float*)d_in[1];
    const float* v  = (const float*)d_in[2];
    const float* Wq = (const float*)d_in[3];
    const float* bq = (const float*)d_in[4];
    const float* Wk = (const float*)d_in[5];
    const float* bk = (const float*)d_in[6];
    const float* Wv = (const float*)d_in[7];
    const float* bv = (const float*)d_in[8];
    const float* Wo = (const float*)d_in[9];
    const float* bo = (const float*)d_in[10];
    float* out = (float*)d_out;

    __half *ih, *il, *wh, *qhp, *qlp, *khp, *vhp;
    cudaGetSymbolAddress((void**)&ih, g_ih);
    cudaGetSymbolAddress((void**)&il, g_il);
    cudaGetSymbolAddress((void**)&wh, g_wh);
    cudaGetSymbolAddress((void**)&qhp, g_qh);
    cudaGetSymbolAddress((void**)&qlp, g_ql);
    cudaGetSymbolAddress((void**)&khp, g_kh);
    cudaGetSymbolAddress((void**)&vhp, g_vh);

    const size_t NX = (size_t)M_ * D_;
    const size_t NW = (size_t)D_ * D_;

    cudaFuncSetAttribute(gemm_mma<1>,
                         cudaFuncAttributeMaxDynamicSharedMemorySize, GEMM_SMEM);
    cudaFuncSetAttribute(gemm_mma<0>,
                         cudaFuncAttributeMaxDynamicSharedMemorySize, GEMM_SMEM);
    cudaFuncSetAttribute(flash_attn_mma,
                         cudaFuncAttributeMaxDynamicSharedMemorySize, FA_SMEM);

    // one launch: split q,k,v (hi+lo) + 4 weights (hi only)
    CArgs ca = {};
    ca.src[0] = q;  ca.h[0] = ih;        ca.l[0] = il;        ca.n4[0] = (int)(NX/4);
    ca.src[1] = k;  ca.h[1] = ih + NX;   ca.l[1] = il + NX;   ca.n4[1] = (int)(NX/4);
    ca.src[2] = v;  ca.h[2] = ih + 2*NX; ca.l[2] = il + 2*NX; ca.n4[2] = (int)(NX/4);
    ca.src[3] = Wq; ca.h[3] = wh;        ca.l[3] = nullptr;   ca.n4[3] = (int)(NW/4);
    ca.src[4] = Wk; ca.h[4] = wh + NW;   ca.l[4] = nullptr;   ca.n4[4] = (int)(NW/4);
    ca.src[5] = Wv; ca.h[5] = wh + 2*NW; ca.l[5] = nullptr;   ca.n4[5] = (int)(NW/4);
    ca.src[6] = Wo; ca.h[6] = wh + 3*NW; ca.l[6] = nullptr;   ca.n4[6] = (int)(NW/4);
    cvt_split7<<<dim3((unsigned)(NX/4/256), 7), 256>>>(ca);

    // fused Q/K/V projections (Q gets hi+lo; K,V hi only)
    GArgs2 gq = {};
    gq.Ah[0] = ih;        gq.Al[0] = il;        gq.Wh[0] = wh;
    gq.Ah[1] = ih + NX;   gq.Al[1] = il + NX;   gq.Wh[1] = wh + NW;
    gq.Ah[2] = ih + 2*NX; gq.Al[2] = il + 2*NX; gq.Wh[2] = wh + 2*NW;
    gq.bias[0] = bq; gq.bias[1] = bk; gq.bias[2] = bv;
    gq.Ch[0] = qhp; gq.Ch[1] = khp; gq.Ch[2] = vhp;
    gq.Cl[0] = qlp; gq.Cl[1] = nullptr; gq.Cl[2] = nullptr;
    gemm_mma<1><<<dim3(D_/128, M_/128, 3), 512, GEMM_SMEM>>>(gq);

    // attention: writes f16 hi/lo output into the (now free) q/k input buffers
    flash_attn_mma<<<dim3(S_/128, B_*H_), 256, FA_SMEM>>>(qhp, qlp, khp, vhp,
                                                           ih, il);

    // output projection (fp32 out)
    GArgs2 go = {};
    go.Ah[0] = ih; go.Al[0] = il;
    go.Wh[0] = wh + 3*NW;
    go.bias[0] = bo;
    go.Cf[0] = out;
    gemm_mma<0><<<dim3(D_/128, M_/128, 1), 512, GEMM_SMEM>>>(go);
}